// round 16
// baseline (speedup 1.0000x reference)
#include <cuda_runtime.h>
#include <cuda_bf16.h>

// ExpmLogm on symmetric 3x3 per-voxel matrices collapses to the identity:
//   eigh(M) -> (S,U); log(exp(S)) = S; U diag(S) U^T = M  (== input).
// Optimal = streaming D2D copy of ~302 MB (irreducible read+write).
//
// Sweep record (kernel time): LDG.128 winning basin = 39.9-41.3us
// (VPT=4 x float4, TPB 128/256) at ~7.5 TB/s wall vs 37.7us floor.
// This round: last untried ISA lever — Blackwell 256-bit global accesses
// (ld/st.global.v8.f32 -> LDG.E.256/STG.E.256). Halves instructions/byte
// and L1tex wavefront-queue entries/byte at identical line traffic.

#define TPB 128        // threads per block
#define V8PT 2         // 32B vectors per thread (64B/thread total)

struct __align__(32) f32x8 { float v[8]; };

__device__ __forceinline__ f32x8 ldg256_cs(const float* p) {
    f32x8 r;
    asm volatile("ld.global.cs.v8.f32 {%0,%1,%2,%3,%4,%5,%6,%7}, [%8];"
                 : "=f"(r.v[0]), "=f"(r.v[1]), "=f"(r.v[2]), "=f"(r.v[3]),
                   "=f"(r.v[4]), "=f"(r.v[5]), "=f"(r.v[6]), "=f"(r.v[7])
                 : "l"(p));
    return r;
}

__device__ __forceinline__ void stg256_cs(float* p, const f32x8& r) {
    asm volatile("st.global.cs.v8.f32 [%0], {%1,%2,%3,%4,%5,%6,%7,%8};"
                 :: "l"(p),
                    "f"(r.v[0]), "f"(r.v[1]), "f"(r.v[2]), "f"(r.v[3]),
                    "f"(r.v[4]), "f"(r.v[5]), "f"(r.v[6]), "f"(r.v[7])
                 : "memory");
}

// Exact-fit path: grid*TPB*V8PT*8 == n floats. Front-batched 256-bit loads.
__global__ __launch_bounds__(TPB) void expmlogm_copy_v8(
    const float* __restrict__ in, float* __restrict__ out) {
    // Each block covers TPB*V8PT contiguous 32B vectors.
    long long base = ((long long)blockIdx.x * (TPB * V8PT) + threadIdx.x) * 8;
    f32x8 a = ldg256_cs(in + base);
    f32x8 b = ldg256_cs(in + base + TPB * 8);
    stg256_cs(out + base, a);
    stg256_cs(out + base + TPB * 8, b);
}

// Generic predicated float4 fallback (non-divisible sizes; unused here).
#define VPT 4
__global__ __launch_bounds__(256) void expmlogm_copy_kernel(
    const float4* __restrict__ in, float4* __restrict__ out, int n4) {
    int base = blockIdx.x * (256 * VPT) + threadIdx.x;
    float4 v[VPT];
    int idx[VPT];
    #pragma unroll
    for (int k = 0; k < VPT; k++) {
        idx[k] = base + k * 256;
        if (idx[k] < n4) v[k] = __ldcs(&in[idx[k]]);
    }
    #pragma unroll
    for (int k = 0; k < VPT; k++) {
        if (idx[k] < n4) __stcs(&out[idx[k]], v[k]);
    }
}

__global__ void expmlogm_copy_tail(const float* __restrict__ in,
                                   float* __restrict__ out,
                                   int start, int n) {
    int i = start + blockIdx.x * blockDim.x + threadIdx.x;
    if (i < n) out[i] = in[i];
}

extern "C" void kernel_launch(void* const* d_in, const int* in_sizes, int n_in,
                              void* d_out, int out_size) {
    const float* x = (const float*)d_in[0];
    float* out = (float*)d_out;
    int n = in_sizes[0];

    const int floats_per_block = TPB * V8PT * 8;  // 2048

    if (n > 0 && n % floats_per_block == 0) {
        // Hot path: n = 37,748,736 = 18432 * 2048.
        expmlogm_copy_v8<<<n / floats_per_block, TPB>>>(x, out);
    } else {
        int n4 = n / 4;
        if (n4 > 0) {
            int per_block = 256 * VPT;
            int blocks = (n4 + per_block - 1) / per_block;
            expmlogm_copy_kernel<<<blocks, 256>>>(
                (const float4*)x, (float4*)out, n4);
        }
        int tail_start = n4 * 4;
        if (n - tail_start > 0) {
            expmlogm_copy_tail<<<1, 128>>>(x, out, tail_start, n);
        }
    }
}

// round 17
// speedup vs baseline: 1.0013x; 1.0013x over previous
#include <cuda_runtime.h>
#include <cuda_bf16.h>

// ExpmLogm on symmetric 3x3 per-voxel matrices collapses to the identity:
//   eigh(M) -> (S,U); log(exp(S)) = S; U diag(S) U^T = M  (== input).
// Optimal = streaming D2D copy of ~302 MB (irreducible read+write).
//
// FINAL — exhaustive sweep (kernel time, ncu):
//   copy path : SM kernel > driver memcpy engine (~42us)
//   VPT       : 1 (42.5) | 4 (39.9-41.3, WIN) | 8 (42.7, occ loss)
//   TPB       : 128 (40.2, best sample) ~= 256 | 512 (43.9, L1tex contention)
//   width     : LDG.128 (WIN) | LDG.256 (41.3, no front-end benefit at
//               issue=3%, worse wavefront pacing)
//   predicates: exact-fit > guarded; ldcs/stcs streaming hints kept.
// Winner: ~7.5 TB/s wall = ~94% of the 37.7us physical floor @ 8 TB/s spec.
// dur_us = saturated copy + ~8+-2us fixed harness overhead (noise).

#define VPT 4          // float4 per thread
#define TPB 128        // threads per block

// Exact-fit path: grid*TPB*VPT == n4, no predicates, front-batched loads.
__global__ __launch_bounds__(TPB) void expmlogm_copy_exact(
    const float4* __restrict__ in, float4* __restrict__ out) {
    int base = blockIdx.x * (TPB * VPT) + threadIdx.x;
    float4 v[VPT];
    #pragma unroll
    for (int k = 0; k < VPT; k++) v[k] = __ldcs(&in[base + k * TPB]);
    #pragma unroll
    for (int k = 0; k < VPT; k++) __stcs(&out[base + k * TPB], v[k]);
}

// Generic predicated path (fallback for non-divisible sizes; unused here).
__global__ __launch_bounds__(TPB) void expmlogm_copy_kernel(
    const float4* __restrict__ in, float4* __restrict__ out, int n4) {
    int base = blockIdx.x * (TPB * VPT) + threadIdx.x;
    float4 v[VPT];
    int idx[VPT];
    #pragma unroll
    for (int k = 0; k < VPT; k++) {
        idx[k] = base + k * TPB;
        if (idx[k] < n4) v[k] = __ldcs(&in[idx[k]]);
    }
    #pragma unroll
    for (int k = 0; k < VPT; k++) {
        if (idx[k] < n4) __stcs(&out[idx[k]], v[k]);
    }
}

__global__ void expmlogm_copy_tail(const float* __restrict__ in,
                                   float* __restrict__ out,
                                   int start, int n) {
    int i = start + blockIdx.x * blockDim.x + threadIdx.x;
    if (i < n) out[i] = in[i];
}

extern "C" void kernel_launch(void* const* d_in, const int* in_sizes, int n_in,
                              void* d_out, int out_size) {
    const float* x = (const float*)d_in[0];
    float* out = (float*)d_out;
    int n = in_sizes[0];

    int n4 = n / 4;
    int per_block = TPB * VPT;

    if (n4 > 0 && n4 % per_block == 0) {
        // Hot path for this problem: n4 = 9,437,184 = 18432 * 512.
        expmlogm_copy_exact<<<n4 / per_block, TPB>>>(
            (const float4*)x, (float4*)out);
    } else if (n4 > 0) {
        int blocks = (n4 + per_block - 1) / per_block;
        expmlogm_copy_kernel<<<blocks, TPB>>>(
            (const float4*)x, (float4*)out, n4);
    }
    int tail_start = n4 * 4;
    if (n - tail_start > 0) {
        expmlogm_copy_tail<<<1, 128>>>(x, out, tail_start, n);
    }
}